// round 15
// baseline (speedup 1.0000x reference)
#include <cuda_runtime.h>
#include <cuda_fp16.h>
#include <cstdint>

// Problem constants
#define BB 8
#define TT 1024
#define HH 1024
#define MM (BB * TT)      // 8192 rows
#define LN_EPS 1e-5f

// HMMA GEMM tiling: CTA 64x128, 8 warps of 32x32, occ 3
#define BM 64
#define BN 128
#define BKE 32                 // fp16 K elems per stage
#define NSTAGE 5
#define STAGE_BYTES 12288      // A: 4KB, B: 8KB
#define GEMM_SMEM (NSTAGE * STAGE_BYTES)   // 61440
#define GTH 256

// msg tiling (assumes wp+wf <= 16 as in dataset: wp=wf=8)
#define MTC 64                 // t-values per block
#define MROWS (MTC + 16)       // 80 resident rows
#define MTHREADS 256

// ---------------------------------------------------------------------------
// Scratch (device globals — allocation-free rule)
// ---------------------------------------------------------------------------
__device__ __half g_xh[MM * HH];
__device__ __half g_mh[MM * HH];
__device__ __half g_rh[MM * HH];
__device__ __half g_wst[HH * HH];   // W_self^T [n][k]
__device__ __half g_wmt[HH * HH];   // W_msg^T
__device__ __half g_wot[HH * HH];   // W_out^T
__device__ __half g_z[MM * HH];     // z in fp16

// ---------------------------------------------------------------------------
// PTX helpers (baseline ISA — compiles at compute_103)
// ---------------------------------------------------------------------------
__device__ __forceinline__ uint32_t smem_u32(const void* p) {
    uint32_t a;
    asm("{ .reg .u64 t; cvta.to.shared.u64 t, %1; cvt.u32.u64 %0, t; }"
        : "=r"(a) : "l"(p));
    return a;
}
__device__ __forceinline__ void cp16(uint32_t dst, const void* src) {
    asm volatile("cp.async.cg.shared.global [%0], [%1], 16;" :: "r"(dst), "l"(src));
}
__device__ __forceinline__ void ldsm4(uint32_t* r, uint32_t a) {
    asm volatile("ldmatrix.sync.aligned.m8n8.x4.shared.b16 {%0,%1,%2,%3}, [%4];"
        : "=r"(r[0]), "=r"(r[1]), "=r"(r[2]), "=r"(r[3]) : "r"(a));
}
__device__ __forceinline__ void mma16816(float* c, const uint32_t* a,
                                         uint32_t b0, uint32_t b1) {
    asm volatile(
        "mma.sync.aligned.m16n8k16.row.col.f32.f16.f16.f32 "
        "{%0,%1,%2,%3}, {%4,%5,%6,%7}, {%8,%9}, {%0,%1,%2,%3};"
        : "+f"(c[0]), "+f"(c[1]), "+f"(c[2]), "+f"(c[3])
        : "r"(a[0]), "r"(a[1]), "r"(a[2]), "r"(a[3]), "r"(b0), "r"(b1));
}

// Tile rows are 64B (32 fp16); 16B chunk index XOR-swizzled with (row>>1)&3.
__device__ __forceinline__ uint32_t ldsm_addr(uint32_t tilebase, int row0, int ks, int lane) {
    const int sub = lane >> 3;
    const int row = row0 + (lane & 7) + ((sub & 1) << 3);
    const int ck  = ks * 2 + (sub >> 1);
    const int swz = ck ^ ((row >> 1) & 3);
    return tilebase + row * 64 + swz * 16;
}

// ---------------------------------------------------------------------------
// Unified prep kernel: blocks [0,1024) do tiled msg + x->fp16;
// blocks [1024, 4096) do the 3 weight transposes (fp32 -> fp16 W^T).
// ---------------------------------------------------------------------------
struct MsgSm {
    float sx[MROWS][128];
    float s_inv[MTC];
    char  s_spk[MROWS];
};
struct TrSm { float tile[32][33]; };
union PrepSm { MsgSm m; TrSm t; };

__global__ __launch_bounds__(MTHREADS)
void prep_kernel(const float* __restrict__ x,
                 const float* __restrict__ qmask,
                 const int* __restrict__ dia_len,
                 const int* __restrict__ wp_p,
                 const int* __restrict__ wf_p,
                 __half* __restrict__ xh, __half* __restrict__ mh,
                 const float* __restrict__ W0, __half* __restrict__ T0,
                 const float* __restrict__ W1, __half* __restrict__ T1,
                 const float* __restrict__ W2, __half* __restrict__ T2)
{
    __shared__ PrepSm sm;
    const int tid = threadIdx.x;
    const int bx  = blockIdx.x;

    if (bx >= 1024) {
        // ---------------- transpose path ----------------
        const int id  = bx - 1024;            // 0..3071
        const int zs  = id >> 10;             // 0..2
        const int rem = id & 1023;
        const int n0 = (rem & 31) * 32, k0 = (rem >> 5) * 32;
        const float* W = (zs == 0) ? W0 : (zs == 1) ? W1 : W2;
        __half* Th     = (zs == 0) ? T0 : (zs == 1) ? T1 : T2;

        const int tx = tid & 31, ty = tid >> 5;   // 32 x 8
        #pragma unroll
        for (int i = 0; i < 4; ++i)
            sm.t.tile[ty + i * 8][tx] = W[(size_t)(k0 + ty + i * 8) * HH + n0 + tx];
        __syncthreads();
        #pragma unroll
        for (int i = 0; i < 4; ++i) {
            const float v = sm.t.tile[tx][ty + i * 8];
            Th[(size_t)(n0 + ty + i * 8) * HH + k0 + tx] = __float2half(v);
        }
        return;
    }

    // ---------------- msg path ----------------
    const int c0 = (bx & 7) * 128;
    const int t0 = ((bx >> 3) & 15) * MTC;
    const int b  = bx >> 7;
    const int wp = *wp_p, wf = *wf_p;
    const int nw = wp + wf + 1;            // 17
    const int L  = dia_len[b];

    const uint32_t sx_base = smem_u32(&sm.m.sx[0][0]);

    // stage x tile rows [t0-wp, t0+MTC-1+wf] (clamped) via cp.async
    #pragma unroll
    for (int p = 0; p < (MROWS * 32) / MTHREADS; ++p) {      // 10 passes
        const int idx = p * MTHREADS + tid;                   // 0..2559
        const int row = idx >> 5;
        const int c4  = idx & 31;
        int gr = t0 - wp + row;
        gr = min(max(gr, 0), TT - 1);
        cp16(sx_base + (row * 128 + c4 * 4) * 4,
             x + ((size_t)(b * TT + gr)) * HH + c0 + c4 * 4);
    }
    asm volatile("cp.async.commit_group;" ::: "memory");

    if (tid < MROWS) {
        int gr = t0 - wp + tid;
        gr = min(max(gr, 0), TT - 1);
        const float q0 = __ldg(qmask + ((size_t)(b * TT + gr) << 1));
        const float q1 = __ldg(qmask + ((size_t)(b * TT + gr) << 1) + 1);
        sm.m.s_spk[tid] = (q1 > q0) ? 1 : 0;
    }
    if (tid >= 128 && tid < 128 + MTC) {
        const int t = tid - 128;
        const int tg = t0 + t;
        int hi = tg + wf; if (hi > L - 1) hi = L - 1;
        int lo = tg - wp; if (lo < 0) lo = 0;
        int cnt = hi - lo + 1; if (cnt < 1) cnt = 1;
        sm.m.s_inv[t] = 0.5f / (float)cnt;
    }

    asm volatile("cp.async.wait_group 0;" ::: "memory");
    __syncthreads();

    const int c2 = (tid & 63) * 2;
    const int tg0 = (tid >> 6) * 16;

    // ---- xh conversion (2 cols x 16 t's per thread) ----
    #pragma unroll
    for (int i = 0; i < 16; ++i) {
        const int t = tg0 + i;
        const float2 v = *(const float2*)&sm.m.sx[wp + t][c2];
        const size_t go = ((size_t)(b * TT + t0 + t)) * HH + c0 + c2;
        *(__half2*)(xh + go) = __floats2half2_rn(v.x, v.y);
    }

    // ---- msg via O(1) sliding windowed sums ----
    float sa0 = 0.f, sa1 = 0.f, s00 = 0.f, s01 = 0.f;
    for (int o = 0; o < nw; ++o) {
        const int row = tg0 + o;
        const int gi = t0 - wp + row;
        if (gi >= 0 && gi <= L - 1) {
            const float2 v = *(const float2*)&sm.m.sx[row][c2];
            sa0 += v.x; sa1 += v.y;
            if (!sm.m.s_spk[row]) { s00 += v.x; s01 += v.y; }
        }
    }
    #pragma unroll
    for (int i = 0; i < 16; ++i) {
        const int tl = tg0 + i;
        const bool spk1 = sm.m.s_spk[tl + wp] != 0;
        const float ch0 = spk1 ? (sa0 - s00) : s00;
        const float ch1 = spk1 ? (sa1 - s01) : s01;
        const float inv = sm.m.s_inv[tl];
        const float m0 = (sa0 + ch0) * inv;
        const float m1 = (sa1 + ch1) * inv;
        const size_t go = ((size_t)(b * TT + t0 + tl)) * HH + c0 + c2;
        *(__half2*)(mh + go) = __floats2half2_rn(m0, m1);

        if (i < 15) {
            const int gi_l = t0 - wp + tl;
            if (gi_l >= 0 && gi_l <= L - 1) {
                const float2 v = *(const float2*)&sm.m.sx[tl][c2];
                sa0 -= v.x; sa1 -= v.y;
                if (!sm.m.s_spk[tl]) { s00 -= v.x; s01 -= v.y; }
            }
            const int re = tl + nw;
            const int gi_e = t0 - wp + re;
            if (re < MROWS && gi_e >= 0 && gi_e <= L - 1) {
                const float2 v = *(const float2*)&sm.m.sx[re][c2];
                sa0 += v.x; sa1 += v.y;
                if (!sm.m.s_spk[re]) { s00 += v.x; s01 += v.y; }
            }
        }
    }
}

// ---------------------------------------------------------------------------
// HMMA GEMM, 5-stage cp.async, CTA 64x128, 8 warps (32x32 each), 256 thr, occ3.
// D = sum_g A_g @ B_g^T   (single fp16 operands)
// mode 0: h = D + b0 + b1; out = nv ? h : x; relu -> out_h (fp16)
// mode 1: z = x + D + b0 -> out_h (fp16)
// ---------------------------------------------------------------------------
__device__ __forceinline__ void load_tile_ca(uint32_t dstbase,
                                             const __half* __restrict__ src,
                                             int r0, int k0, int tid, int npass)
{
    #pragma unroll
    for (int j = 0; j < 2; ++j) {
        if (j >= npass) break;
        const int cc  = j * GTH + tid;
        const int row = cc >> 2;
        const int ck  = cc & 3;
        const int swz = ck ^ ((row >> 1) & 3);
        cp16(dstbase + row * 64 + swz * 16,
             src + (size_t)(r0 + row) * HH + k0 + ck * 8);
    }
}

__global__ __launch_bounds__(GTH, 3)
void hmma_gemm_kernel(const __half* __restrict__ A0, const __half* __restrict__ B0,
                      const __half* __restrict__ A1, const __half* __restrict__ B1,
                      int ngroups,
                      const float* __restrict__ b0v, const float* __restrict__ b1v,
                      const float* __restrict__ x, const int* __restrict__ dia_len,
                      int mode,
                      __half* __restrict__ out_h)
{
    extern __shared__ char smem[];
    const uint32_t sbase = smem_u32(smem);
    const int tid  = threadIdx.x;
    const int wid  = tid >> 5, lane = tid & 31;
    const int warp_m = wid & 1;      // 2 groups along M (32 rows each)
    const int warp_n = wid >> 1;     // 4 groups along N (32 cols each)
    const int n0 = blockIdx.x * BN;
    const int m0 = blockIdx.y * BM;

    const int Lb = dia_len[m0 >> 10];
    const bool tile_live = (mode != 0) || ((m0 & (TT - 1)) < Lb);

    float acc[2][4][4];
    #pragma unroll
    for (int i = 0; i < 2; ++i)
        #pragma unroll
        for (int j = 0; j < 4; ++j)
            #pragma unroll
            for (int k = 0; k < 4; ++k) acc[i][j][k] = 0.f;

    if (tile_live) {
        const int NC = ngroups * (HH / BKE);

        auto do_load = [&](int cc, int stage) {
            const __half* A = (cc < 32) ? A0 : A1;
            const __half* B = (cc < 32) ? B0 : B1;
            const int k0 = (cc & 31) * BKE;
            const uint32_t sb = sbase + stage * STAGE_BYTES;
            load_tile_ca(sb,        A, m0, k0, tid, 1);   // 64x32 = 4KB
            load_tile_ca(sb + 4096, B, n0, k0, tid, 2);   // 128x32 = 8KB
            asm volatile("cp.async.commit_group;" ::: "memory");
        };

        do_load(0, 0);
        do_load(1, 1);
        do_load(2, 2);
        do_load(3, 3);

        int stage = 0;
        int nstage = 4;
        for (int c = 0; c < NC; ++c) {
            const int rem = NC - 1 - c;
            if (rem >= 3)      { asm volatile("cp.async.wait_group 3;" ::: "memory"); }
            else if (rem == 2) { asm volatile("cp.async.wait_group 2;" ::: "memory"); }
            else if (rem == 1) { asm volatile("cp.async.wait_group 1;" ::: "memory"); }
            else               { asm volatile("cp.async.wait_group 0;" ::: "memory"); }
            __syncthreads();

            if (c + 4 < NC) do_load(c + 4, nstage);

            const uint32_t sb = sbase + stage * STAGE_BYTES;
            const uint32_t sA = sb, sB = sb + 4096;

            #pragma unroll
            for (int ks = 0; ks < 2; ++ks) {
                uint32_t af[2][4];
                #pragma unroll
                for (int mf = 0; mf < 2; ++mf)
                    ldsm4(af[mf], ldsm_addr(sA, warp_m * 32 + mf * 16, ks, lane));
                #pragma unroll
                for (int nb = 0; nb < 2; ++nb) {
                    uint32_t bf[4];
                    ldsm4(bf, ldsm_addr(sB, warp_n * 32 + nb * 16, ks, lane));
                    #pragma unroll
                    for (int mf = 0; mf < 2; ++mf) {
                        mma16816(acc[mf][nb * 2],     af[mf], bf[0], bf[2]);
                        mma16816(acc[mf][nb * 2 + 1], af[mf], bf[1], bf[3]);
                    }
                }
            }
            stage = (stage == NSTAGE - 1) ? 0 : stage + 1;
            nstage = (nstage == NSTAGE - 1) ? 0 : nstage + 1;
        }
    }

    // ---- epilogue ----
    const int groupID = lane >> 2;
    const int qc = (lane & 3) * 2;

    float2 biasv[4];
    #pragma unroll
    for (int nf = 0; nf < 4; ++nf) {
        const int col = n0 + warp_n * 32 + nf * 8 + qc;
        if (mode == 0) {
            biasv[nf].x = __ldg(b0v + col)     + __ldg(b1v + col);
            biasv[nf].y = __ldg(b0v + col + 1) + __ldg(b1v + col + 1);
        } else {
            biasv[nf].x = __ldg(b0v + col);
            biasv[nf].y = __ldg(b0v + col + 1);
        }
    }

    #pragma unroll
    for (int mf = 0; mf < 2; ++mf) {
        #pragma unroll
        for (int half = 0; half < 2; ++half) {
            const int m = m0 + warp_m * 32 + mf * 16 + groupID + half * 8;
            const size_t rb = (size_t)m * HH;
            const bool nv = (mode == 0) ? ((m & (TT - 1)) < Lb) : true;
            #pragma unroll
            for (int nf = 0; nf < 4; ++nf) {
                const int col = n0 + warp_n * 32 + nf * 8 + qc;
                float v0 = acc[mf][nf][half * 2 + 0] + biasv[nf].x;
                float v1 = acc[mf][nf][half * 2 + 1] + biasv[nf].y;
                if (mode == 0) {
                    if (!nv) {
                        const float2 xv = *(const float2*)(x + rb + col);
                        v0 = xv.x; v1 = xv.y;
                    }
                    v0 = fmaxf(v0, 0.f); v1 = fmaxf(v1, 0.f);
                } else {
                    const float2 xv = *(const float2*)(x + rb + col);
                    v0 += xv.x; v1 += xv.y;
                }
                *(__half2*)(out_h + rb + col) = __floats2half2_rn(v0, v1);
            }
        }
    }
}

// ---------------------------------------------------------------------------
// LayerNorm: barrier-free, one warp per row. 256 thr = 8 rows/block.
// Lane loads 32 halves (4 coalesced uint4), shfl-tree reduces, normalizes.
// ---------------------------------------------------------------------------
__global__ __launch_bounds__(256)
void ln_kernel(const __half* __restrict__ z,
               const float* __restrict__ gamma,
               const float* __restrict__ beta,
               float* __restrict__ out)
{
    const int tid  = threadIdx.x;
    const int wid  = tid >> 5, lane = tid & 31;
    const int row  = blockIdx.x * 8 + wid;
    const size_t rb = (size_t)row * HH;

    // 4 chunks: chunk c covers cols c*256 + lane*8 .. +7 (coalesced 16B/lane)
    float f[4][8];
    float s = 0.f, ss = 0.f;
    #pragma unroll
    for (int c = 0; c < 4; ++c) {
        const int col = c * 256 + lane * 8;
        const uint4 raw = *(const uint4*)(z + rb + col);
        const __half2* hp = (const __half2*)&raw;
        #pragma unroll
        for (int i = 0; i < 4; ++i) {
            const float2 v = __half22float2(hp[i]);
            f[c][i * 2]     = v.x;
            f[c][i * 2 + 1] = v.y;
        }
        #pragma unroll
        for (int i = 0; i < 8; ++i) { s += f[c][i]; ss += f[c][i] * f[c][i]; }
    }
    #pragma unroll
    for (int off = 16; off; off >>= 1) {
        s  += __shfl_xor_sync(0xFFFFFFFFu, s,  off);
        ss += __shfl_xor_sync(0xFFFFFFFFu, ss, off);
    }
    const float mean = s * (1.f / HH);
    const float var  = ss * (1.f / HH) - mean * mean;
    const float inv  = rsqrtf(var + LN_EPS);

    #pragma unroll
    for (int c = 0; c < 4; ++c) {
        const int col = c * 256 + lane * 8;
        const float4 g0 = *(const float4*)(gamma + col);
        const float4 g1 = *(const float4*)(gamma + col + 4);
        const float4 b0 = *(const float4*)(beta  + col);
        const float4 b1 = *(const float4*)(beta  + col + 4);
        float4 o0, o1;
        o0.x = g0.x * (f[c][0] - mean) * inv + b0.x;
        o0.y = g0.y * (f[c][1] - mean) * inv + b0.y;
        o0.z = g0.z * (f[c][2] - mean) * inv + b0.z;
        o0.w = g0.w * (f[c][3] - mean) * inv + b0.w;
        o1.x = g1.x * (f[c][4] - mean) * inv + b1.x;
        o1.y = g1.y * (f[c][5] - mean) * inv + b1.y;
        o1.z = g1.z * (f[c][6] - mean) * inv + b1.z;
        o1.w = g1.w * (f[c][7] - mean) * inv + b1.w;
        *(float4*)(out + rb + col)     = o0;
        *(float4*)(out + rb + col + 4) = o1;
    }
}

// ---------------------------------------------------------------------------
// Launch
// ---------------------------------------------------------------------------
extern "C" void kernel_launch(void* const* d_in, const int* in_sizes, int n_in,
                              void* d_out, int out_size)
{
    const float* x      = (const float*)d_in[0];
    const float* qmask  = (const float*)d_in[1];
    const int*   dia    = (const int*)  d_in[2];
    const int*   wp     = (const int*)  d_in[3];
    const int*   wf     = (const int*)  d_in[4];
    const float* W_msg  = (const float*)d_in[5];
    const float* b_msg  = (const float*)d_in[6];
    const float* W_self = (const float*)d_in[7];
    const float* b_self = (const float*)d_in[8];
    const float* W_out  = (const float*)d_in[9];
    const float* b_out  = (const float*)d_in[10];
    const float* gamma  = (const float*)d_in[11];
    const float* beta   = (const float*)d_in[12];
    float* out = (float*)d_out;

    __half *xh, *mh, *rh, *wst, *wmt, *wot, *z;
    cudaGetSymbolAddress((void**)&xh, g_xh);
    cudaGetSymbolAddress((void**)&mh, g_mh);
    cudaGetSymbolAddress((void**)&rh, g_rh);
    cudaGetSymbolAddress((void**)&wst, g_wst);
    cudaGetSymbolAddress((void**)&wmt, g_wmt);
    cudaGetSymbolAddress((void**)&wot, g_wot);
    cudaGetSymbolAddress((void**)&z, g_z);

    cudaFuncSetAttribute(hmma_gemm_kernel,
                         cudaFuncAttributeMaxDynamicSharedMemorySize, GEMM_SMEM);

    // prep: msg (1024 blocks) + 3 weight transposes (3072 blocks) in one launch
    prep_kernel<<<4096, MTHREADS>>>(x, qmask, dia, wp, wf, xh, mh,
                                    W_self, wst, W_msg, wmt, W_out, wot);

    dim3 ggrid(HH / BN, MM / BM);   // (8, 128)
    // GEMM1: x@W_self + msg@W_msg -> relu/select -> r (fp16)
    hmma_gemm_kernel<<<ggrid, GTH, GEMM_SMEM>>>(
        xh, wst, mh, wmt, 2,
        b_self, b_msg, x, dia, 0, rh);
    // GEMM2: r@W_out + b_out + x -> z (fp16)
    hmma_gemm_kernel<<<ggrid, GTH, GEMM_SMEM>>>(
        rh, wot, nullptr, nullptr, 1,
        b_out, nullptr, x, dia, 1, z);

    ln_kernel<<<MM / 8, 256>>>(z, gamma, beta, out);
}

// round 16
// speedup vs baseline: 1.0093x; 1.0093x over previous
#include <cuda_runtime.h>
#include <cuda_fp16.h>
#include <cstdint>

// Problem constants
#define BB 8
#define TT 1024
#define HH 1024
#define MM (BB * TT)      // 8192 rows
#define LN_EPS 1e-5f

// HMMA GEMM tiling: CTA 64x128, 8 warps of 32x32, occ 3
#define BM 64
#define BN 128
#define BKE 32                 // fp16 K elems per stage
#define NSTAGE 5
#define STAGE_BYTES 12288      // A: 4KB, B: 8KB
#define GEMM_SMEM (NSTAGE * STAGE_BYTES)   // 61440
#define GTH 256

// msg tiling (assumes wp+wf <= 16 as in dataset: wp=wf=8)
#define MTC 64                 // t-values per block
#define MROWS (MTC + 16)       // 80 resident rows
#define MTHREADS 256

// ---------------------------------------------------------------------------
// Scratch (device globals — allocation-free rule)
// ---------------------------------------------------------------------------
__device__ __half g_xh[MM * HH];
__device__ __half g_mh[MM * HH];
__device__ __half g_rh[MM * HH];
__device__ __half g_wst[HH * HH];   // W_self^T [n][k]
__device__ __half g_wmt[HH * HH];   // W_msg^T
__device__ __half g_wot[HH * HH];   // W_out^T
__device__ __half g_z[MM * HH];     // z in fp16
__device__ float  g_sum[MM];        // per-row sum of z (fp32, pre-rounding)
__device__ float  g_ssum[MM];       // per-row sum of z^2

// ---------------------------------------------------------------------------
// PTX helpers (baseline ISA — compiles at compute_103)
// ---------------------------------------------------------------------------
__device__ __forceinline__ uint32_t smem_u32(const void* p) {
    uint32_t a;
    asm("{ .reg .u64 t; cvta.to.shared.u64 t, %1; cvt.u32.u64 %0, t; }"
        : "=r"(a) : "l"(p));
    return a;
}
__device__ __forceinline__ void cp16(uint32_t dst, const void* src) {
    asm volatile("cp.async.cg.shared.global [%0], [%1], 16;" :: "r"(dst), "l"(src));
}
__device__ __forceinline__ void ldsm4(uint32_t* r, uint32_t a) {
    asm volatile("ldmatrix.sync.aligned.m8n8.x4.shared.b16 {%0,%1,%2,%3}, [%4];"
        : "=r"(r[0]), "=r"(r[1]), "=r"(r[2]), "=r"(r[3]) : "r"(a));
}
__device__ __forceinline__ void mma16816(float* c, const uint32_t* a,
                                         uint32_t b0, uint32_t b1) {
    asm volatile(
        "mma.sync.aligned.m16n8k16.row.col.f32.f16.f16.f32 "
        "{%0,%1,%2,%3}, {%4,%5,%6,%7}, {%8,%9}, {%0,%1,%2,%3};"
        : "+f"(c[0]), "+f"(c[1]), "+f"(c[2]), "+f"(c[3])
        : "r"(a[0]), "r"(a[1]), "r"(a[2]), "r"(a[3]), "r"(b0), "r"(b1));
}

// Tile rows are 64B (32 fp16); 16B chunk index XOR-swizzled with (row>>1)&3.
__device__ __forceinline__ uint32_t ldsm_addr(uint32_t tilebase, int row0, int ks, int lane) {
    const int sub = lane >> 3;
    const int row = row0 + (lane & 7) + ((sub & 1) << 3);
    const int ck  = ks * 2 + (sub >> 1);
    const int swz = ck ^ ((row >> 1) & 3);
    return tilebase + row * 64 + swz * 16;
}

// ---------------------------------------------------------------------------
// Unified prep kernel: blocks [0,1024) do tiled msg + x->fp16 (+ stats zero);
// blocks [1024, 4096) do the 3 weight transposes (fp32 -> fp16 W^T).
// ---------------------------------------------------------------------------
struct MsgSm {
    float sx[MROWS][128];
    float s_inv[MTC];
    char  s_spk[MROWS];
};
struct TrSm { float tile[32][33]; };
union PrepSm { MsgSm m; TrSm t; };

__global__ __launch_bounds__(MTHREADS)
void prep_kernel(const float* __restrict__ x,
                 const float* __restrict__ qmask,
                 const int* __restrict__ dia_len,
                 const int* __restrict__ wp_p,
                 const int* __restrict__ wf_p,
                 __half* __restrict__ xh, __half* __restrict__ mh,
                 const float* __restrict__ W0, __half* __restrict__ T0,
                 const float* __restrict__ W1, __half* __restrict__ T1,
                 const float* __restrict__ W2, __half* __restrict__ T2)
{
    __shared__ PrepSm sm;
    const int tid = threadIdx.x;
    const int bx  = blockIdx.x;

    if (bx >= 1024) {
        // ---------------- transpose path ----------------
        const int id  = bx - 1024;            // 0..3071
        const int zs  = id >> 10;             // 0..2
        const int rem = id & 1023;
        const int n0 = (rem & 31) * 32, k0 = (rem >> 5) * 32;
        const float* W = (zs == 0) ? W0 : (zs == 1) ? W1 : W2;
        __half* Th     = (zs == 0) ? T0 : (zs == 1) ? T1 : T2;

        const int tx = tid & 31, ty = tid >> 5;   // 32 x 8
        #pragma unroll
        for (int i = 0; i < 4; ++i)
            sm.t.tile[ty + i * 8][tx] = W[(size_t)(k0 + ty + i * 8) * HH + n0 + tx];
        __syncthreads();
        #pragma unroll
        for (int i = 0; i < 4; ++i) {
            const float v = sm.t.tile[tx][ty + i * 8];
            Th[(size_t)(n0 + ty + i * 8) * HH + k0 + tx] = __float2half(v);
        }
        return;
    }

    // ---------------- msg path ----------------
    const int c0 = (bx & 7) * 128;
    const int t0 = ((bx >> 3) & 15) * MTC;
    const int b  = bx >> 7;
    const int wp = *wp_p, wf = *wf_p;
    const int nw = wp + wf + 1;            // 17
    const int L  = dia_len[b];

    // zero LN stats for this (b, t0) row range (one block per range: c0 == 0)
    if (c0 == 0 && tid < MTC) {
        g_sum[b * TT + t0 + tid]  = 0.f;
        g_ssum[b * TT + t0 + tid] = 0.f;
    }

    const uint32_t sx_base = smem_u32(&sm.m.sx[0][0]);

    // stage x tile rows [t0-wp, t0+MTC-1+wf] (clamped) via cp.async
    #pragma unroll
    for (int p = 0; p < (MROWS * 32) / MTHREADS; ++p) {      // 10 passes
        const int idx = p * MTHREADS + tid;                   // 0..2559
        const int row = idx >> 5;
        const int c4  = idx & 31;
        int gr = t0 - wp + row;
        gr = min(max(gr, 0), TT - 1);
        cp16(sx_base + (row * 128 + c4 * 4) * 4,
             x + ((size_t)(b * TT + gr)) * HH + c0 + c4 * 4);
    }
    asm volatile("cp.async.commit_group;" ::: "memory");

    if (tid < MROWS) {
        int gr = t0 - wp + tid;
        gr = min(max(gr, 0), TT - 1);
        const float q0 = __ldg(qmask + ((size_t)(b * TT + gr) << 1));
        const float q1 = __ldg(qmask + ((size_t)(b * TT + gr) << 1) + 1);
        sm.m.s_spk[tid] = (q1 > q0) ? 1 : 0;
    }
    if (tid >= 128 && tid < 128 + MTC) {
        const int t = tid - 128;
        const int tg = t0 + t;
        int hi = tg + wf; if (hi > L - 1) hi = L - 1;
        int lo = tg - wp; if (lo < 0) lo = 0;
        int cnt = hi - lo + 1; if (cnt < 1) cnt = 1;
        sm.m.s_inv[t] = 0.5f / (float)cnt;
    }

    asm volatile("cp.async.wait_group 0;" ::: "memory");
    __syncthreads();

    const int c2 = (tid & 63) * 2;
    const int tg0 = (tid >> 6) * 16;

    // ---- xh conversion (2 cols x 16 t's per thread) ----
    #pragma unroll
    for (int i = 0; i < 16; ++i) {
        const int t = tg0 + i;
        const float2 v = *(const float2*)&sm.m.sx[wp + t][c2];
        const size_t go = ((size_t)(b * TT + t0 + t)) * HH + c0 + c2;
        *(__half2*)(xh + go) = __floats2half2_rn(v.x, v.y);
    }

    // ---- msg via O(1) sliding windowed sums ----
    float sa0 = 0.f, sa1 = 0.f, s00 = 0.f, s01 = 0.f;
    for (int o = 0; o < nw; ++o) {
        const int row = tg0 + o;
        const int gi = t0 - wp + row;
        if (gi >= 0 && gi <= L - 1) {
            const float2 v = *(const float2*)&sm.m.sx[row][c2];
            sa0 += v.x; sa1 += v.y;
            if (!sm.m.s_spk[row]) { s00 += v.x; s01 += v.y; }
        }
    }
    #pragma unroll
    for (int i = 0; i < 16; ++i) {
        const int tl = tg0 + i;
        const bool spk1 = sm.m.s_spk[tl + wp] != 0;
        const float ch0 = spk1 ? (sa0 - s00) : s00;
        const float ch1 = spk1 ? (sa1 - s01) : s01;
        const float inv = sm.m.s_inv[tl];
        const float m0 = (sa0 + ch0) * inv;
        const float m1 = (sa1 + ch1) * inv;
        const size_t go = ((size_t)(b * TT + t0 + tl)) * HH + c0 + c2;
        *(__half2*)(mh + go) = __floats2half2_rn(m0, m1);

        if (i < 15) {
            const int gi_l = t0 - wp + tl;
            if (gi_l >= 0 && gi_l <= L - 1) {
                const float2 v = *(const float2*)&sm.m.sx[tl][c2];
                sa0 -= v.x; sa1 -= v.y;
                if (!sm.m.s_spk[tl]) { s00 -= v.x; s01 -= v.y; }
            }
            const int re = tl + nw;
            const int gi_e = t0 - wp + re;
            if (re < MROWS && gi_e >= 0 && gi_e <= L - 1) {
                const float2 v = *(const float2*)&sm.m.sx[re][c2];
                sa0 += v.x; sa1 += v.y;
                if (!sm.m.s_spk[re]) { s00 += v.x; s01 += v.y; }
            }
        }
    }
}

// ---------------------------------------------------------------------------
// HMMA GEMM, 5-stage cp.async, CTA 64x128, 8 warps (32x32 each), 256 thr, occ3.
// mode 0: h = D + b0 + b1; out = nv ? h : x; relu -> out_h (fp16)
// mode 1: z = x + D + b0 -> out_h (fp16); also accumulates per-row LN stats
//         (sum, sum^2 of fp32 z) into g_sum/g_ssum via quad-reduced atomics.
// ---------------------------------------------------------------------------
__device__ __forceinline__ void load_tile_ca(uint32_t dstbase,
                                             const __half* __restrict__ src,
                                             int r0, int k0, int tid, int npass)
{
    #pragma unroll
    for (int j = 0; j < 2; ++j) {
        if (j >= npass) break;
        const int cc  = j * GTH + tid;
        const int row = cc >> 2;
        const int ck  = cc & 3;
        const int swz = ck ^ ((row >> 1) & 3);
        cp16(dstbase + row * 64 + swz * 16,
             src + (size_t)(r0 + row) * HH + k0 + ck * 8);
    }
}

__global__ __launch_bounds__(GTH, 3)
void hmma_gemm_kernel(const __half* __restrict__ A0, const __half* __restrict__ B0,
                      const __half* __restrict__ A1, const __half* __restrict__ B1,
                      int ngroups,
                      const float* __restrict__ b0v, const float* __restrict__ b1v,
                      const float* __restrict__ x, const int* __restrict__ dia_len,
                      int mode,
                      __half* __restrict__ out_h)
{
    extern __shared__ char smem[];
    const uint32_t sbase = smem_u32(smem);
    const int tid  = threadIdx.x;
    const int wid  = tid >> 5, lane = tid & 31;
    const int warp_m = wid & 1;      // 2 groups along M (32 rows each)
    const int warp_n = wid >> 1;     // 4 groups along N (32 cols each)
    const int n0 = blockIdx.x * BN;
    const int m0 = blockIdx.y * BM;

    const int Lb = dia_len[m0 >> 10];
    const bool tile_live = (mode != 0) || ((m0 & (TT - 1)) < Lb);

    float acc[2][4][4];
    #pragma unroll
    for (int i = 0; i < 2; ++i)
        #pragma unroll
        for (int j = 0; j < 4; ++j)
            #pragma unroll
            for (int k = 0; k < 4; ++k) acc[i][j][k] = 0.f;

    if (tile_live) {
        const int NC = ngroups * (HH / BKE);

        auto do_load = [&](int cc, int stage) {
            const __half* A = (cc < 32) ? A0 : A1;
            const __half* B = (cc < 32) ? B0 : B1;
            const int k0 = (cc & 31) * BKE;
            const uint32_t sb = sbase + stage * STAGE_BYTES;
            load_tile_ca(sb,        A, m0, k0, tid, 1);   // 64x32 = 4KB
            load_tile_ca(sb + 4096, B, n0, k0, tid, 2);   // 128x32 = 8KB
            asm volatile("cp.async.commit_group;" ::: "memory");
        };

        do_load(0, 0);
        do_load(1, 1);
        do_load(2, 2);
        do_load(3, 3);

        int stage = 0;
        int nstage = 4;
        for (int c = 0; c < NC; ++c) {
            const int rem = NC - 1 - c;
            if (rem >= 3)      { asm volatile("cp.async.wait_group 3;" ::: "memory"); }
            else if (rem == 2) { asm volatile("cp.async.wait_group 2;" ::: "memory"); }
            else if (rem == 1) { asm volatile("cp.async.wait_group 1;" ::: "memory"); }
            else               { asm volatile("cp.async.wait_group 0;" ::: "memory"); }
            __syncthreads();

            if (c + 4 < NC) do_load(c + 4, nstage);

            const uint32_t sb = sbase + stage * STAGE_BYTES;
            const uint32_t sA = sb, sB = sb + 4096;

            #pragma unroll
            for (int ks = 0; ks < 2; ++ks) {
                uint32_t af[2][4];
                #pragma unroll
                for (int mf = 0; mf < 2; ++mf)
                    ldsm4(af[mf], ldsm_addr(sA, warp_m * 32 + mf * 16, ks, lane));
                #pragma unroll
                for (int nb = 0; nb < 2; ++nb) {
                    uint32_t bf[4];
                    ldsm4(bf, ldsm_addr(sB, warp_n * 32 + nb * 16, ks, lane));
                    #pragma unroll
                    for (int mf = 0; mf < 2; ++mf) {
                        mma16816(acc[mf][nb * 2],     af[mf], bf[0], bf[2]);
                        mma16816(acc[mf][nb * 2 + 1], af[mf], bf[1], bf[3]);
                    }
                }
            }
            stage = (stage == NSTAGE - 1) ? 0 : stage + 1;
            nstage = (nstage == NSTAGE - 1) ? 0 : nstage + 1;
        }
    }

    // ---- epilogue ----
    const int groupID = lane >> 2;
    const int qc = (lane & 3) * 2;

    float2 biasv[4];
    #pragma unroll
    for (int nf = 0; nf < 4; ++nf) {
        const int col = n0 + warp_n * 32 + nf * 8 + qc;
        if (mode == 0) {
            biasv[nf].x = __ldg(b0v + col)     + __ldg(b1v + col);
            biasv[nf].y = __ldg(b0v + col + 1) + __ldg(b1v + col + 1);
        } else {
            biasv[nf].x = __ldg(b0v + col);
            biasv[nf].y = __ldg(b0v + col + 1);
        }
    }

    #pragma unroll
    for (int mf = 0; mf < 2; ++mf) {
        #pragma unroll
        for (int half = 0; half < 2; ++half) {
            const int m = m0 + warp_m * 32 + mf * 16 + groupID + half * 8;
            const size_t rb = (size_t)m * HH;
            const bool nv = (mode == 0) ? ((m & (TT - 1)) < Lb) : true;
            float rs = 0.f, rss = 0.f;
            #pragma unroll
            for (int nf = 0; nf < 4; ++nf) {
                const int col = n0 + warp_n * 32 + nf * 8 + qc;
                float v0 = acc[mf][nf][half * 2 + 0] + biasv[nf].x;
                float v1 = acc[mf][nf][half * 2 + 1] + biasv[nf].y;
                if (mode == 0) {
                    if (!nv) {
                        const float2 xv = *(const float2*)(x + rb + col);
                        v0 = xv.x; v1 = xv.y;
                    }
                    v0 = fmaxf(v0, 0.f); v1 = fmaxf(v1, 0.f);
                } else {
                    const float2 xv = *(const float2*)(x + rb + col);
                    v0 += xv.x; v1 += xv.y;
                    rs  += v0 + v1;
                    rss += v0 * v0 + v1 * v1;
                }
                *(__half2*)(out_h + rb + col) = __floats2half2_rn(v0, v1);
            }
            if (mode != 0) {
                // reduce across the 4 lanes of this row's quad, then atomics
                rs  += __shfl_xor_sync(0xFFFFFFFFu, rs,  1);
                rss += __shfl_xor_sync(0xFFFFFFFFu, rss, 1);
                rs  += __shfl_xor_sync(0xFFFFFFFFu, rs,  2);
                rss += __shfl_xor_sync(0xFFFFFFFFu, rss, 2);
                if ((lane & 3) == 0) {
                    atomicAdd(&g_sum[m],  rs);
                    atomicAdd(&g_ssum[m], rss);
                }
            }
        }
    }
}

// ---------------------------------------------------------------------------
// LayerNorm: reduction-free (stats precomputed by GEMM2). 2 rows / 256-thr blk.
// ---------------------------------------------------------------------------
__global__ __launch_bounds__(256)
void ln_kernel(const __half* __restrict__ z,
               const float* __restrict__ gamma,
               const float* __restrict__ beta,
               float* __restrict__ out)
{
    const int tid = threadIdx.x;
    const int grp = tid >> 7;            // 0/1: which row
    const int lt  = tid & 127;           // thread within row
    const int row = blockIdx.x * 2 + grp;

    const float mean = g_sum[row] * (1.f / HH);
    const float var  = g_ssum[row] * (1.f / HH) - mean * mean;
    const float inv  = rsqrtf(var + LN_EPS);

    const size_t base = (size_t)row * HH + lt * 8;
    const uint4 raw = *(const uint4*)(z + base);
    float f[8];
    {
        const __half2* hp = (const __half2*)&raw;
        #pragma unroll
        for (int i = 0; i < 4; ++i) {
            const float2 v = __half22float2(hp[i]);
            f[i * 2]     = v.x;
            f[i * 2 + 1] = v.y;
        }
    }

    const float4 g0 = *(const float4*)(gamma + lt * 8);
    const float4 g1 = *(const float4*)(gamma + lt * 8 + 4);
    const float4 b0 = *(const float4*)(beta  + lt * 8);
    const float4 b1 = *(const float4*)(beta  + lt * 8 + 4);

    float4 o0, o1;
    o0.x = g0.x * (f[0] - mean) * inv + b0.x;
    o0.y = g0.y * (f[1] - mean) * inv + b0.y;
    o0.z = g0.z * (f[2] - mean) * inv + b0.z;
    o0.w = g0.w * (f[3] - mean) * inv + b0.w;
    o1.x = g1.x * (f[4] - mean) * inv + b1.x;
    o1.y = g1.y * (f[5] - mean) * inv + b1.y;
    o1.z = g1.z * (f[6] - mean) * inv + b1.z;
    o1.w = g1.w * (f[7] - mean) * inv + b1.w;
    *(float4*)(out + base)     = o0;
    *(float4*)(out + base + 4) = o1;
}

// ---------------------------------------------------------------------------
// Launch
// ---------------------------------------------------------------------------
extern "C" void kernel_launch(void* const* d_in, const int* in_sizes, int n_in,
                              void* d_out, int out_size)
{
    const float* x      = (const float*)d_in[0];
    const float* qmask  = (const float*)d_in[1];
    const int*   dia    = (const int*)  d_in[2];
    const int*   wp     = (const int*)  d_in[3];
    const int*   wf     = (const int*)  d_in[4];
    const float* W_msg  = (const float*)d_in[5];
    const float* b_msg  = (const float*)d_in[6];
    const float* W_self = (const float*)d_in[7];
    const float* b_self = (const float*)d_in[8];
    const float* W_out  = (const float*)d_in[9];
    const float* b_out  = (const float*)d_in[10];
    const float* gamma  = (const float*)d_in[11];
    const float* beta   = (const float*)d_in[12];
    float* out = (float*)d_out;

    __half *xh, *mh, *rh, *wst, *wmt, *wot, *z;
    cudaGetSymbolAddress((void**)&xh, g_xh);
    cudaGetSymbolAddress((void**)&mh, g_mh);
    cudaGetSymbolAddress((void**)&rh, g_rh);
    cudaGetSymbolAddress((void**)&wst, g_wst);
    cudaGetSymbolAddress((void**)&wmt, g_wmt);
    cudaGetSymbolAddress((void**)&wot, g_wot);
    cudaGetSymbolAddress((void**)&z, g_z);

    cudaFuncSetAttribute(hmma_gemm_kernel,
                         cudaFuncAttributeMaxDynamicSharedMemorySize, GEMM_SMEM);

    // prep: msg + stats zero (1024 blocks) + 3 weight transposes (3072 blocks)
    prep_kernel<<<4096, MTHREADS>>>(x, qmask, dia, wp, wf, xh, mh,
                                    W_self, wst, W_msg, wmt, W_out, wot);

    dim3 ggrid(HH / BN, MM / BM);   // (8, 128)
    // GEMM1: x@W_self + msg@W_msg -> relu/select -> r (fp16)
    hmma_gemm_kernel<<<ggrid, GTH, GEMM_SMEM>>>(
        xh, wst, mh, wmt, 2,
        b_self, b_msg, x, dia, 0, rh);
    // GEMM2: r@W_out + b_out + x -> z (fp16) + LN stats
    hmma_gemm_kernel<<<ggrid, GTH, GEMM_SMEM>>>(
        rh, wot, nullptr, nullptr, 1,
        b_out, nullptr, x, dia, 1, z);

    ln_kernel<<<MM / 2, 256>>>(z, gamma, beta, out);
}